// round 17
// baseline (speedup 1.0000x reference)
#include <cuda_runtime.h>
#include <cuda_bf16.h>
#include <cstdint>

// Problem constants
#define Bc 2
#define Sc 2048
#define Dc 1024
#define Hc 16
#define DKc 64
#define Mc (Bc*Sc)   // 4096
#define NTILES 32    // Sc / 64

// ---------------- scratch (no allocations allowed) ----------------
__device__ __nv_bfloat16 g_Xh[3][Mc*Dc];
__device__ __nv_bfloat16 g_Xl[3][Mc*Dc];
__device__ __nv_bfloat16 g_Wh[4][Dc*Dc];   // [k][n] as given
__device__ __nv_bfloat16 g_Wl[4][Dc*Dc];
__device__ __nv_bfloat16 g_Qh[Mc*Dc], g_Ql[Mc*Dc];
__device__ __nv_bfloat16 g_Kh[Mc*Dc], g_Kl[Mc*Dc];
__device__ __nv_bfloat16 g_Vh[Mc*Dc], g_Vl[Mc*Dc];
__device__ __nv_bfloat16 g_Ch[Mc*Dc], g_Cl[Mc*Dc];
__device__ float g_Vtile[Bc*Hc*NTILES*DKc];
__device__ float g_Vsuf[Bc*Hc*(NTILES+1)*DKc];
__device__ float g_pm[Bc*Sc];
__device__ int   g_mask_mode;

// ---------------- helpers ----------------
__device__ __forceinline__ uint32_t smem_u32(const void* p) {
    return (uint32_t)__cvta_generic_to_shared(p);
}

#define MMA(c, a, b0, b1)                                                     \
    asm volatile(                                                             \
        "mma.sync.aligned.m16n8k16.row.col.f32.bf16.bf16.f32 "                \
        "{%0,%1,%2,%3},{%4,%5,%6,%7},{%8,%9},{%0,%1,%2,%3};\n"                \
        : "+f"((c)[0]), "+f"((c)[1]), "+f"((c)[2]), "+f"((c)[3])              \
        : "r"((a)[0]), "r"((a)[1]), "r"((a)[2]), "r"((a)[3]),                 \
          "r"(b0), "r"(b1));

#define LDMX4(r, addr)                                                        \
    asm volatile("ldmatrix.sync.aligned.m8n8.x4.shared.b16 {%0,%1,%2,%3}, [%4];" \
        : "=r"((r)[0]), "=r"((r)[1]), "=r"((r)[2]), "=r"((r)[3]) : "r"(addr));

#define LDMX4T(r, addr)                                                       \
    asm volatile("ldmatrix.sync.aligned.m8n8.x4.trans.shared.b16 {%0,%1,%2,%3}, [%4];" \
        : "=r"((r)[0]), "=r"((r)[1]), "=r"((r)[2]), "=r"((r)[3]) : "r"(addr));

#define CPA16(dst, src)                                                       \
    asm volatile("cp.async.cg.shared.global [%0], [%1], 16;\n"                \
        :: "r"(dst), "l"(src));
#define CPA_COMMIT() asm volatile("cp.async.commit_group;\n" ::: "memory")
#define CPA_WAIT0()  asm volatile("cp.async.wait_group 0;\n" ::: "memory")
#define CPA_WAIT1()  asm volatile("cp.async.wait_group 1;\n" ::: "memory")

__device__ __forceinline__ uint32_t packh2(float a, float b) {
    __nv_bfloat162 t;
    t.x = __float2bfloat16(a);
    t.y = __float2bfloat16(b);
    return *reinterpret_cast<uint32_t*>(&t);
}
__device__ __forceinline__ uint32_t packl2(float a, float b) {
    float ra = a - __bfloat162float(__float2bfloat16(a));
    float rb = b - __bfloat162float(__float2bfloat16(b));
    return packh2(ra, rb);
}

// ---------------- padding-mask dtype sniffing ----------------
__global__ void detect_mask_k(const unsigned int* __restrict__ mm) {
    __shared__ int okInt, okFloat;
    if (threadIdx.x == 0) { okInt = 1; okFloat = 1; }
    __syncthreads();
    for (int i = threadIdx.x; i < 1024; i += blockDim.x) {
        unsigned int v = mm[i];
        if (v > 1u) okInt = 0;
        if (v != 0u && v != 0x3F800000u) okFloat = 0;
    }
    __syncthreads();
    if (threadIdx.x == 0)
        g_mask_mode = okInt ? 1 : (okFloat ? 2 : 0);
}

__global__ void expand_mask_k(const void* __restrict__ mraw) {
    int i = blockIdx.x * blockDim.x + threadIdx.x;
    if (i >= Bc * Sc) return;
    int mode = g_mask_mode;
    float v;
    if (mode == 1)       v = (((const int*)mraw)[i] != 0) ? 1.f : 0.f;
    else if (mode == 2)  v = (((const float*)mraw)[i] != 0.f) ? 1.f : 0.f;
    else                 v = (((const unsigned char*)mraw)[i] != 0) ? 1.f : 0.f;
    g_pm[i] = v;
}

// ---------------- fp32 -> bf16 hi/lo split (all 7 tensors, one launch) ----------------
struct SplitArgs { const float* src[7]; };

__global__ void split_all_k(SplitArgs sa) {
    const int id = blockIdx.y;
    const int n4 = (id < 3) ? (Mc * Dc / 4) : (Dc * Dc / 4);
    int i = blockIdx.x * blockDim.x + threadIdx.x;
    if (i >= n4) return;
    __nv_bfloat16 *ph, *pl;
    if (id < 3) { ph = g_Xh[id]; pl = g_Xl[id]; }
    else        { ph = g_Wh[id - 3]; pl = g_Wl[id - 3]; }
    float4 v = ((const float4*)sa.src[id])[i];
    float a[4] = {v.x, v.y, v.z, v.w};
    __nv_bfloat162 h0, h1, l0, l1;
    h0.x = __float2bfloat16(a[0]); h0.y = __float2bfloat16(a[1]);
    h1.x = __float2bfloat16(a[2]); h1.y = __float2bfloat16(a[3]);
    l0.x = __float2bfloat16(a[0] - __bfloat162float(h0.x));
    l0.y = __float2bfloat16(a[1] - __bfloat162float(h0.y));
    l1.x = __float2bfloat16(a[2] - __bfloat162float(h1.x));
    l1.y = __float2bfloat16(a[3] - __bfloat162float(h1.y));
    ((__nv_bfloat162*)ph)[i * 2]     = h0;
    ((__nv_bfloat162*)ph)[i * 2 + 1] = h1;
    ((__nv_bfloat162*)pl)[i * 2]     = l0;
    ((__nv_bfloat162*)pl)[i * 2 + 1] = l1;
}

// ---------------- V tile sums + suffix scan (parallel) ----------------
__global__ void vtile_k() {
    const int bh = blockIdx.x, t = blockIdx.y, dk = threadIdx.x;
    const size_t base = (size_t)bh * Sc * DKc + (size_t)t * 64 * DKc + dk;
    float s = 0.f;
#pragma unroll 8
    for (int j = 0; j < 64; j++) {
        size_t idx = base + (size_t)j * DKc;
        s += __bfloat162float(g_Vh[idx]) + __bfloat162float(g_Vl[idx]);
    }
    g_Vtile[((size_t)bh * NTILES + t) * DKc + dk] = s;
}

__global__ void vscan_k() {
    const int bh = blockIdx.x, dk = threadIdx.x;
    float acc = 0.f;
    float* out = g_Vsuf + (size_t)bh * (NTILES + 1) * DKc + dk;
    out[NTILES * DKc] = 0.f;
    for (int t = NTILES - 1; t >= 0; t--) {
        acc += g_Vtile[((size_t)bh * NTILES + t) * DKc + dk];
        out[t * DKc] = acc;
    }
}

// ---------------- bf16 split-GEMM: 128x128x32, 4 warps (2x2), 64x64 warp tile ----------
// 3-stage cp.async ring, ONE barrier per K-step (stage written at iter kb is the
// stage consumed at iter kb-1, protected by the top barrier of iter kb).
struct GemmBias { const float* b[4]; };

#define ASTR 40
#define BSTR 136
#define A_ELE (128*ASTR)
#define B_ELE (32*BSTR)
#define G_STAGE (2*A_ELE + 2*B_ELE)      // 18944 bf16 = 37888 B
#define GEMM_SMEM (3*G_STAGE*2)          // 113664 bytes

__global__ __launch_bounds__(128, 2) void gemm_k(GemmBias gb, int mode_in, float* Cf) {
    extern __shared__ __align__(16) __nv_bfloat16 dsm[];
    const int mode = (mode_in < 0) ? (int)blockIdx.z : mode_in;
    const __nv_bfloat16 *Ah, *Al, *Bh, *Bl;
    __nv_bfloat16 *Oh = nullptr, *Ol = nullptr;
    if (mode < 3) {
        Ah = g_Xh[mode]; Al = g_Xl[mode];
        Bh = g_Wh[mode]; Bl = g_Wl[mode];
        Oh = (mode == 0) ? g_Qh : (mode == 1) ? g_Kh : g_Vh;
        Ol = (mode == 0) ? g_Ql : (mode == 1) ? g_Kl : g_Vl;
    } else {
        Ah = g_Ch; Al = g_Cl; Bh = g_Wh[3]; Bl = g_Wl[3];
    }
    const float* bias = gb.b[mode];

    const int tid = threadIdx.x;
    const int lane = tid & 31;
    const int wid = tid >> 5;              // 0..3
    const int wm = wid >> 1, wn = wid & 1; // 2 x 2 warp grid, 64x64 tiles
    const int g = lane >> 2, tg = lane & 3;
    const int sub = lane >> 3, rr = lane & 7;
    const int mBase = blockIdx.y * 128, nBase = blockIdx.x * 128;

#define GEMM_ISSUE(kb, s)                                                      \
    {                                                                          \
        __nv_bfloat16* stg = dsm + (s) * G_STAGE;                              \
        _Pragma("unroll")                                                      \
        for (int i = 0; i < 4; i++) {                                          \
            int c = tid + 128 * i;                                             \
            int ar = c >> 2, ac = (c & 3) * 8;                                 \
            size_t aoff = (size_t)(mBase + ar) * Dc + (kb) * 32 + ac;          \
            CPA16(smem_u32(stg + ar * ASTR + ac), Ah + aoff);                  \
            CPA16(smem_u32(stg + A_ELE + ar * ASTR + ac), Al + aoff);          \
            int br = c >> 4, bc = (c & 15) * 8;                                \
            size_t boff = (size_t)((kb) * 32 + br) * Dc + nBase + bc;          \
            CPA16(smem_u32(stg + 2*A_ELE + br * BSTR + bc), Bh + boff);        \
            CPA16(smem_u32(stg + 2*A_ELE + B_ELE + br * BSTR + bc), Bl + boff);\
        }                                                                      \
        CPA_COMMIT();                                                          \
    }

    float acc[4][8][4];
#pragma unroll
    for (int i = 0; i < 4; i++)
#pragma unroll
        for (int j = 0; j < 8; j++)
#pragma unroll
            for (int k = 0; k < 4; k++) acc[i][j][k] = 0.f;

    GEMM_ISSUE(0, 0);
    GEMM_ISSUE(1, 1);

    const int KIT = Dc / 32;   // 32
    for (int kb = 0; kb < KIT; kb++) {
        const int st = kb % 3;
        if (kb + 1 < KIT) { CPA_WAIT1(); }   // tile kb complete (in-order groups)
        else              { CPA_WAIT0(); }
        __syncthreads();                     // all warps done with stage (kb-1)%3
        if (kb + 2 < KIT) GEMM_ISSUE(kb + 2, (kb + 2) % 3);   // == (kb-1)%3: safe

        const __nv_bfloat16* pAh = dsm + st * G_STAGE;
        const __nv_bfloat16* pAl = pAh + A_ELE;
        const __nv_bfloat16* pBh = pAh + 2 * A_ELE;
        const __nv_bfloat16* pBl = pBh + B_ELE;

#pragma unroll
        for (int ks = 0; ks < 2; ks++) {
            uint32_t fah[4][4], fal[4][4];
#pragma unroll
            for (int mf = 0; mf < 4; mf++) {
                int ar = wm * 64 + mf * 16 + (sub & 1) * 8 + rr;
                int ac = ks * 16 + (sub >> 1) * 8;
                LDMX4(fah[mf], smem_u32(pAh + ar * ASTR + ac));
                LDMX4(fal[mf], smem_u32(pAl + ar * ASTR + ac));
            }
#pragma unroll
            for (int nb = 0; nb < 4; nb++) {
                uint32_t bh_[4], bl_[4];
                int br = ks * 16 + (sub & 1) * 8 + rr;
                int bc = wn * 64 + nb * 16 + (sub >> 1) * 8;
                LDMX4T(bh_, smem_u32(pBh + br * BSTR + bc));
                LDMX4T(bl_, smem_u32(pBl + br * BSTR + bc));
#pragma unroll
                for (int mf = 0; mf < 4; mf++) {
                    MMA(acc[mf][2*nb],     fah[mf], bh_[0], bh_[1]);
                    MMA(acc[mf][2*nb + 1], fah[mf], bh_[2], bh_[3]);
                }
#pragma unroll
                for (int mf = 0; mf < 4; mf++) {
                    MMA(acc[mf][2*nb],     fah[mf], bl_[0], bl_[1]);
                    MMA(acc[mf][2*nb + 1], fah[mf], bl_[2], bl_[3]);
                }
#pragma unroll
                for (int mf = 0; mf < 4; mf++) {
                    MMA(acc[mf][2*nb],     fal[mf], bh_[0], bh_[1]);
                    MMA(acc[mf][2*nb + 1], fal[mf], bh_[2], bh_[3]);
                }
            }
        }
    }

    // epilogue
#pragma unroll
    for (int mf = 0; mf < 4; mf++) {
        int r0 = mBase + wm * 64 + mf * 16 + g;
        int r1 = r0 + 8;
#pragma unroll
        for (int nf = 0; nf < 8; nf++) {
            int n = nBase + wn * 64 + nf * 8 + tg * 2;
            float bv0 = bias[n], bv1 = bias[n + 1];
            float v00 = acc[mf][nf][0] + bv0, v01 = acc[mf][nf][1] + bv1;
            float v10 = acc[mf][nf][2] + bv0, v11 = acc[mf][nf][3] + bv1;
            if (mode == 3) {
                *(float2*)(Cf + (size_t)r0 * Dc + n) = make_float2(v00, v01);
                *(float2*)(Cf + (size_t)r1 * Dc + n) = make_float2(v10, v11);
            } else {
                int h = n >> 6, dk = n & 63;
#pragma unroll
                for (int p = 0; p < 2; p++) {
                    int r = p ? r1 : r0;
                    float a0 = p ? v10 : v00, a1 = p ? v11 : v01;
                    int b = r >> 11, s = r & 2047;
                    size_t idx = (((size_t)(b * Hc + h)) * Sc + s) * DKc + dk;
                    *(uint32_t*)(Oh + idx) = packh2(a0, a1);
                    *(uint32_t*)(Ol + idx) = packl2(a0, a1);
                }
            }
        }
    }
}

// ---------------- tensor-core flash attention, 2-stage + suffix skip ----------------
// Single barrier per tile: issue for stage st^1 happens AFTER the top barrier,
// which guarantees all warps are done with that stage (consumed at iter t-1).
#define AT_A 4608
#define AT_STAGE (4*AT_A)
#define AT_PMS_OFF (2*AT_STAGE)
#define ATTN_SMEM (2*AT_STAGE*2 + 2*64*4)   // 74240 bytes

__global__ __launch_bounds__(128) void attn_k() {
    extern __shared__ __align__(16) __nv_bfloat16 adsm[];
    float* pmsf = (float*)(adsm + AT_PMS_OFF);

    const int tid = threadIdx.x;
    const int lane = tid & 31;
    const int wid = tid >> 5;
    const int g = lane >> 2, tg = lane & 3;
    const int sub = lane >> 3, rr = lane & 7;
    const int bh = blockIdx.y, b = bh >> 4, h = bh & 15;
    const int qblk = (int)gridDim.x - 1 - (int)blockIdx.x;   // longest CTAs first
    const int q0 = qblk * 64;
    const int nT = qblk + 1;
    const size_t base = (size_t)bh * Sc * DKc;

#define ATTN_ISSUE(t, s)                                                       \
    {                                                                          \
        __nv_bfloat16* stg = adsm + (s) * AT_STAGE;                            \
        size_t tb = base + (size_t)((t) * 64) * DKc;                           \
        _Pragma("unroll")                                                      \
        for (int k2 = 0; k2 < 4; k2++) {                                       \
            int c = tid + k2 * 128;                                            \
            int row = c >> 3, col = (c & 7) * 8;                               \
            size_t off = tb + (size_t)row * DKc + col;                         \
            int d = row * 72 + col;                                            \
            CPA16(smem_u32(stg + d), g_Kh + off);                              \
            CPA16(smem_u32(stg + AT_A + d), g_Kl + off);                       \
            CPA16(smem_u32(stg + 2*AT_A + d), g_Vh + off);                     \
            CPA16(smem_u32(stg + 3*AT_A + d), g_Vl + off);                     \
        }                                                                      \
        if (tid < 16)                                                          \
            CPA16(smem_u32(pmsf + (s) * 64 + tid * 4),                         \
                  g_pm + b * Sc + (t) * 64 + tid * 4);                         \
        CPA_COMMIT();                                                          \
    }

    ATTN_ISSUE(0, 0);
    {
        __nv_bfloat16* qstg = adsm + AT_STAGE;
        for (int c = tid; c < 64 * 8; c += 128) {
            int row = c >> 3, col = (c & 7) * 8;
            size_t off = base + (size_t)(q0 + row) * DKc + col;
            *(uint4*)(qstg + row * 72 + col)        = *(const uint4*)(g_Qh + off);
            *(uint4*)(qstg + AT_A + row * 72 + col) = *(const uint4*)(g_Ql + off);
        }
    }
    __syncthreads();
    uint32_t qh[4][4], ql[4][4];
    {
        const __nv_bfloat16* qstg = adsm + AT_STAGE;
#pragma unroll
        for (int kb = 0; kb < 4; kb++) {
            int arow = wid * 16 + (sub & 1) * 8 + rr;
            int acol = kb * 16 + (sub >> 1) * 8;
            LDMX4(qh[kb], smem_u32(qstg + arow * 72 + acol));
            LDMX4(ql[kb], smem_u32(qstg + AT_A + arow * 72 + acol));
        }
    }

    float o[8][4];
#pragma unroll
    for (int i = 0; i < 8; i++)
#pragma unroll
        for (int k = 0; k < 4; k++) o[i][k] = 0.f;
    float sum0 = 0.f, sum1 = 0.f;
    const int row0 = q0 + wid * 16 + g, row1 = row0 + 8;

    for (int t = 0; t < nT; t++) {
        const int st = t & 1;
        const int kv0 = t * 64;
        CPA_WAIT0();            // tile t complete
        __syncthreads();        // all warps done with stage st^1 (and Q extract at t=0)
        if (t + 1 < nT) ATTN_ISSUE(t + 1, st ^ 1);

        const __nv_bfloat16* sKh = adsm + st * AT_STAGE;
        const __nv_bfloat16* sKl = sKh + AT_A;
        const __nv_bfloat16* sVh = sKh + 2 * AT_A;
        const __nv_bfloat16* sVl = sKh + 3 * AT_A;
        const float* pms = pmsf + st * 64;

        // S = Q K^T  (split, 3-term)
        float s[8][4];
#pragma unroll
        for (int i = 0; i < 8; i++)
#pragma unroll
            for (int k = 0; k < 4; k++) s[i][k] = 0.f;
#pragma unroll
        for (int kb = 0; kb < 4; kb++) {
            uint32_t bKh[4][4], bKl[4][4];
#pragma unroll
            for (int jj = 0; jj < 4; jj++) {
                int krow = jj * 16 + (sub >> 1) * 8 + rr;
                int kcol = kb * 16 + (sub & 1) * 8;
                LDMX4(bKh[jj], smem_u32(sKh + krow * 72 + kcol));
                LDMX4(bKl[jj], smem_u32(sKl + krow * 72 + kcol));
            }
#pragma unroll
            for (int jj = 0; jj < 4; jj++) {
                MMA(s[2*jj],     qh[kb], bKh[jj][0], bKh[jj][1]);
                MMA(s[2*jj + 1], qh[kb], bKh[jj][2], bKh[jj][3]);
            }
#pragma unroll
            for (int jj = 0; jj < 4; jj++) {
                MMA(s[2*jj],     qh[kb], bKl[jj][0], bKl[jj][1]);
                MMA(s[2*jj + 1], qh[kb], bKl[jj][2], bKl[jj][3]);
            }
#pragma unroll
            for (int jj = 0; jj < 4; jj++) {
                MMA(s[2*jj],     ql[kb], bKh[jj][0], bKh[jj][1]);
                MMA(s[2*jj + 1], ql[kb], bKh[jj][2], bKh[jj][3]);
            }
        }

        // mask + exp, re-pack as P A-fragments
        uint32_t ph[4][4], pl[4][4];
#pragma unroll
        for (int j = 0; j < 8; j++) {
            int cg = kv0 + j * 8 + tg * 2;
            float2 mv = *(float2*)&pms[j * 8 + tg * 2];
            float sc0 = (cg     > row0 || mv.x != 0.f) ? 1e-10f : s[j][0] * 0.125f;
            float sc1 = (cg + 1 > row0 || mv.y != 0.f) ? 1e-10f : s[j][1] * 0.125f;
            float sc2 = (cg     > row1 || mv.x != 0.f) ? 1e-10f : s[j][2] * 0.125f;
            float sc3 = (cg + 1 > row1 || mv.y != 0.f) ? 1e-10f : s[j][3] * 0.125f;
            float e0 = __expf(sc0), e1 = __expf(sc1);
            float e2 = __expf(sc2), e3 = __expf(sc3);
            sum0 += e0 + e1;
            sum1 += e2 + e3;
            int tt = j >> 1;
            if ((j & 1) == 0) {
                ph[tt][0] = packh2(e0, e1); ph[tt][1] = packh2(e2, e3);
                pl[tt][0] = packl2(e0, e1); pl[tt][1] = packl2(e2, e3);
            } else {
                ph[tt][2] = packh2(e0, e1); ph[tt][3] = packh2(e2, e3);
                pl[tt][2] = packl2(e0, e1); pl[tt][3] = packl2(e2, e3);
            }
        }

        // O += P V  (split, 3-term)
#pragma unroll
        for (int tt = 0; tt < 4; tt++) {
            uint32_t vh_[4][4], vl_[4][4];
#pragma unroll
            for (int dd = 0; dd < 4; dd++) {
                int vrow = tt * 16 + (sub & 1) * 8 + rr;
                int vcol = dd * 16 + (sub >> 1) * 8;
                LDMX4T(vh_[dd], smem_u32(sVh + vrow * 72 + vcol));
                LDMX4T(vl_[dd], smem_u32(sVl + vrow * 72 + vcol));
            }
#pragma unroll
            for (int dd = 0; dd < 4; dd++) {
                MMA(o[2*dd],     ph[tt], vh_[dd][0], vh_[dd][1]);
                MMA(o[2*dd + 1], ph[tt], vh_[dd][2], vh_[dd][3]);
            }
#pragma unroll
            for (int dd = 0; dd < 4; dd++) {
                MMA(o[2*dd],     ph[tt], vl_[dd][0], vl_[dd][1]);
                MMA(o[2*dd + 1], ph[tt], vl_[dd][2], vl_[dd][3]);
            }
#pragma unroll
            for (int dd = 0; dd < 4; dd++) {
                MMA(o[2*dd],     pl[tt], vh_[dd][0], vh_[dd][1]);
                MMA(o[2*dd + 1], pl[tt], vh_[dd][2], vh_[dd][3]);
            }
        }
    }

    // future keys: per-lane-owned o elements get the fp32 suffix sum
    {
        const float* suf = g_Vsuf + ((size_t)bh * (NTILES + 1) + nT) * DKc;
#pragma unroll
        for (int nf = 0; nf < 8; nf++) {
            int col = nf * 8 + tg * 2;
            float vA = suf[col], vB = suf[col + 1];
            o[nf][0] += vA; o[nf][1] += vB;
            o[nf][2] += vA; o[nf][3] += vB;
        }
    }

    sum0 += __shfl_xor_sync(0xFFFFFFFFu, sum0, 1);
    sum0 += __shfl_xor_sync(0xFFFFFFFFu, sum0, 2);
    sum1 += __shfl_xor_sync(0xFFFFFFFFu, sum1, 1);
    sum1 += __shfl_xor_sync(0xFFFFFFFFu, sum1, 2);
    const float cnt = (float)(Sc - nT * 64);
    sum0 += cnt;
    sum1 += cnt;
    float inv0 = 1.f / sum0, inv1 = 1.f / sum1;

#pragma unroll
    for (int nf = 0; nf < 8; nf++) {
        int dk = nf * 8 + tg * 2;
        float v00 = o[nf][0] * inv0, v01 = o[nf][1] * inv0;
        float v10 = o[nf][2] * inv1, v11 = o[nf][3] * inv1;
        size_t i0 = ((size_t)(b * Sc + row0)) * Dc + h * DKc + dk;
        size_t i1 = ((size_t)(b * Sc + row1)) * Dc + h * DKc + dk;
        *(uint32_t*)(g_Ch + i0) = packh2(v00, v01);
        *(uint32_t*)(g_Cl + i0) = packl2(v00, v01);
        *(uint32_t*)(g_Ch + i1) = packh2(v10, v11);
        *(uint32_t*)(g_Cl + i1) = packl2(v10, v11);
    }
}

// ---------------- launch ----------------
extern "C" void kernel_launch(void* const* d_in, const int* in_sizes, int n_in,
                              void* d_out, int out_size) {
    const float* query = (const float*)d_in[0];
    const float* key   = (const float*)d_in[1];
    const float* value = (const float*)d_in[2];
    const void*  pmask = d_in[3];
    const float* Wq = (const float*)d_in[4];
    const float* bq = (const float*)d_in[5];
    const float* Wk = (const float*)d_in[6];
    const float* bk = (const float*)d_in[7];
    const float* Wv = (const float*)d_in[8];
    const float* bv = (const float*)d_in[9];
    const float* Wo = (const float*)d_in[10];
    const float* bo = (const float*)d_in[11];
    float* out = (float*)d_out;

    cudaFuncSetAttribute(gemm_k, cudaFuncAttributeMaxDynamicSharedMemorySize, GEMM_SMEM);
    cudaFuncSetAttribute(attn_k, cudaFuncAttributeMaxDynamicSharedMemorySize, ATTN_SMEM);

    detect_mask_k<<<1, 256>>>((const unsigned int*)pmask);
    expand_mask_k<<<(Bc * Sc + 255) / 256, 256>>>(pmask);

    SplitArgs sa;
    sa.src[0] = query; sa.src[1] = key; sa.src[2] = value;
    sa.src[3] = Wq; sa.src[4] = Wk; sa.src[5] = Wv; sa.src[6] = Wo;
    const int nAct4 = Mc * Dc / 4;
    dim3 gSplit((nAct4 + 255) / 256, 7);
    split_all_k<<<gSplit, 256>>>(sa);

    GemmBias gb;
    gb.b[0] = bq; gb.b[1] = bk; gb.b[2] = bv; gb.b[3] = bo;

    dim3 gQKV(Dc / 128, Mc / 128, 3);   // (8, 32, 3)
    gemm_k<<<gQKV, 128, GEMM_SMEM>>>(gb, -1, nullptr);

    dim3 gVt(Bc * Hc, NTILES);
    vtile_k<<<gVt, DKc>>>();
    vscan_k<<<Bc * Hc, DKc>>>();

    dim3 gAttn(Sc / 64, Bc * Hc);       // (32, 32)
    attn_k<<<gAttn, 128, ATTN_SMEM>>>();

    dim3 gOut(Dc / 128, Mc / 128);      // (8, 32)
    gemm_k<<<gOut, 128, GEMM_SMEM>>>(gb, 3, out);
}